// round 14
// baseline (speedup 1.0000x reference)
#include <cuda_runtime.h>

// ---------------------------------------------------------------------------
// Problem shape (fixed by setup_inputs): [B=4, C=16, T=32, H=128, W=128] fp32
// out = (total, L_main, L_temp) as 3 fp32 scalars.
//
// Math: with e = x_star - x_tgt (linearity), e_low = D^T(De) where D = first
// K=4 orthonormal DCT-II rows. Temporal-diff energy = c^T (Q Q^T) c with
// c = De, Q[n,s] = D[n,s+1]-D[n,s]. DC row of D is constant -> Q row 0 == 0,
// so only c1..c3 are needed. Charbonnier ~ |e| (abs error <= eps = 1e-6).
//
// R14: R13's adjacent-2-column kernel with the occupancy cap raised from 4
// to 5 blocks/SM via __launch_bounds__(256,5) -> 51-reg cap, 40 warps/SM
// (was 32 at regs=64). Evidence: the only knob that has ever moved DRAM
// throughput on this problem is per-SM outstanding-load count (1-col 5.2
// TB/s vs 2-col 5.85 TB/s); +25% warps extends that lever. The two |e|
// accumulators per column are merged into one to shave register demand.
// Grid=512 still a single wave (capacity 740 at 5 blocks/SM).
// Failure signature if ptxas spills: L1% > ~18 and DRAM bytes inflate.
// ---------------------------------------------------------------------------
constexpr int T_DIM  = 32;
constexpr int HW     = 128 * 128;      // 16384
constexpr int HW4    = HW / 4;         // 4096 float4 per (b,c,t) plane
constexpr int BC     = 4 * 16;         // 64
constexpr int BLOCK  = 256;
constexpr int NITEM  = BC * HW4;       // 262144 fiber columns (float4 wide)
constexpr int NBLK   = NITEM / (2 * BLOCK);  // 512 blocks, 2 adjacent cols/thread

constexpr double N_MAIN = 33554432.0;  // B*C*T*H*W
constexpr double N_TEMP = 32505856.0;  // B*C*(T-1)*H*W
constexpr double TAU    = 0.1;

// ---------------------------------------------------------------------------
// Compile-time DCT: D[n][t] = 0.25 * cos(pi*(2t+1)*n/64)   (sqrt(2/32)=0.25)
// ---------------------------------------------------------------------------
constexpr double PI_D = 3.141592653589793238462643383279502884;

__host__ __device__ constexpr double dcos(double x) {
    while (x >  PI_D) x -= 2.0 * PI_D;
    while (x < -PI_D) x += 2.0 * PI_D;
    double x2 = x * x;
    double term = 1.0, sum = 1.0;
    for (int k = 1; k <= 18; ++k) {
        term *= -x2 / ((2.0 * k - 1.0) * (2.0 * k));
        sum += term;
    }
    return sum;
}
__host__ __device__ constexpr double Dc(int n, int t) {
    return 0.25 * dcos(PI_D * (2.0 * t + 1.0) * (double)n / 64.0);
}
__host__ __device__ constexpr double Qc(int n, int s) { return Dc(n, s + 1) - Dc(n, s); }
__host__ __device__ constexpr double Mc(int n, int m) {
    double s = 0.0;
    for (int i = 0; i < T_DIM - 1; ++i) s += Qc(n, i) * Qc(m, i);
    return s;
}

// ---------------------------------------------------------------------------
// Scratch: per-block partials + self-resetting completion counter.
// atomicInc(&g_count, NBLK-1) wraps to 0 when the last block arrives, so the
// counter is 0 again at the start of every graph replay. No cleanup kernel.
// ---------------------------------------------------------------------------
__device__ double   g_part_main[NBLK];
__device__ double   g_part_temp[NBLK];
__device__ unsigned g_count = 0;

struct Acc {
    float4 c1, c2, c3;
    float  m;        // single |e| accumulator per column (reg-lean)
};

__device__ __forceinline__ void proc(const float4& a, const float4& b,
                                     float d1, float d2, float d3, Acc& s) {
    float e0 = a.x - b.x, e1 = a.y - b.y, e2 = a.z - b.z, e3 = a.w - b.w;
    s.m += (fabsf(e0) + fabsf(e1)) + (fabsf(e2) + fabsf(e3));
    s.c1.x = fmaf(d1, e0, s.c1.x); s.c1.y = fmaf(d1, e1, s.c1.y);
    s.c1.z = fmaf(d1, e2, s.c1.z); s.c1.w = fmaf(d1, e3, s.c1.w);
    s.c2.x = fmaf(d2, e0, s.c2.x); s.c2.y = fmaf(d2, e1, s.c2.y);
    s.c2.z = fmaf(d2, e2, s.c2.z); s.c2.w = fmaf(d2, e3, s.c2.w);
    s.c3.x = fmaf(d3, e0, s.c3.x); s.c3.y = fmaf(d3, e1, s.c3.y);
    s.c3.z = fmaf(d3, e2, s.c3.z); s.c3.w = fmaf(d3, e3, s.c3.w);
}

// Template-unrolled T loop: coefficients are constexpr locals per step ->
// FFMA immediates in SASS. Two ADJACENT position slots per step, all four
// loads issued before the arithmetic for per-step MLP.
template <int t>
__device__ __forceinline__ void step_all(const float4* __restrict__ pa1,
                                         const float4* __restrict__ pb1,
                                         Acc& s1, Acc& s2) {
    if constexpr (t < T_DIM) {
        constexpr float d1 = (float)Dc(1, t);
        constexpr float d2 = (float)Dc(2, t);
        constexpr float d3 = (float)Dc(3, t);
        float4 a1 = pa1[t * HW4];
        float4 b1 = pb1[t * HW4];
        float4 a2 = pa1[t * HW4 + BLOCK];   // adjacent column: +4KB
        float4 b2 = pb1[t * HW4 + BLOCK];
        proc(a1, b1, d1, d2, d3, s1);
        proc(a2, b2, d1, d2, d3, s2);
        step_all<t + 1>(pa1, pb1, s1, s2);
    }
}

__device__ __forceinline__ float quad_form(float a, float b, float c) {
    constexpr float M11 = (float)Mc(1, 1);
    constexpr float M22 = (float)Mc(2, 2);
    constexpr float M33 = (float)Mc(3, 3);
    constexpr float M12 = (float)(2.0 * Mc(1, 2));
    constexpr float M13 = (float)(2.0 * Mc(1, 3));
    constexpr float M23 = (float)(2.0 * Mc(2, 3));
    float q = M11 * a * a;
    q = fmaf(M22 * b, b, q);
    q = fmaf(M33 * c, c, q);
    q = fmaf(M12 * a, b, q);
    q = fmaf(M13 * a, c, q);
    q = fmaf(M23 * b, c, q);
    return q;
}

__device__ __forceinline__ float quad4(const Acc& s) {
    return (quad_form(s.c1.x, s.c2.x, s.c3.x) + quad_form(s.c1.y, s.c2.y, s.c3.y))
         + (quad_form(s.c1.z, s.c2.z, s.c3.z) + quad_form(s.c1.w, s.c2.w, s.c3.w));
}

__device__ __forceinline__ double warp_sum(double v) {
#pragma unroll
    for (int o = 16; o > 0; o >>= 1)
        v += __shfl_down_sync(0xFFFFFFFFu, v, o);
    return v;
}

__global__ void __launch_bounds__(BLOCK, 5)
loss_fused_kernel(const float* __restrict__ xs, const float* __restrict__ xt,
                  float* __restrict__ out) {
    const int tid = threadIdx.x;
    // Block b owns items [b*512, b*512+512): thread handles g1 = b*512+tid
    // and g2 = g1 + 256 (adjacent). 512 <= HW4, same bc for both columns.
    const int g1  = blockIdx.x * (2 * BLOCK) + tid;
    const int bc  = g1 >> 12;          // / 4096
    const int hw  = g1 & (HW4 - 1);    // % 4096

    const float4* pa1 = reinterpret_cast<const float4*>(xs) + (size_t)bc * (T_DIM * HW4) + hw;
    const float4* pb1 = reinterpret_cast<const float4*>(xt) + (size_t)bc * (T_DIM * HW4) + hw;

    Acc s1 = {}, s2 = {};

    step_all<0>(pa1, pb1, s1, s2);

    double tempv = (double)quad4(s1) + (double)quad4(s2);
    double mainv = (double)(s1.m + s2.m);

    // ---- intra-block reduce: warp shuffle + one shared stage ----
    const int lane = tid & 31;
    const int warp = tid >> 5;
    __shared__ double sm[BLOCK / 32];
    __shared__ double st[BLOCK / 32];

    mainv = warp_sum(mainv);
    tempv = warp_sum(tempv);
    if (lane == 0) { sm[warp] = mainv; st[warp] = tempv; }
    __syncthreads();

    __shared__ bool is_last;
    if (warp == 0) {
        double vm = (lane < BLOCK / 32) ? sm[lane] : 0.0;
        double vt = (lane < BLOCK / 32) ? st[lane] : 0.0;
#pragma unroll
        for (int o = 4; o > 0; o >>= 1) {
            vm += __shfl_down_sync(0xFFFFFFFFu, vm, o);
            vt += __shfl_down_sync(0xFFFFFFFFu, vt, o);
        }
        if (lane == 0) {
            g_part_main[blockIdx.x] = vm;
            g_part_temp[blockIdx.x] = vt;
            __threadfence();
            // wraps to 0 when old == NBLK-1 -> self-resetting across replays
            is_last = (atomicInc(&g_count, NBLK - 1) == NBLK - 1);
        }
    }
    __syncthreads();

    // ---- last-arriving block: deterministic fixed-order global reduce ----
    if (is_last) {
        double vm = 0.0, vt = 0.0;
#pragma unroll
        for (int i = tid; i < NBLK; i += BLOCK) {
            vm += __ldcg(&g_part_main[i]);
            vt += __ldcg(&g_part_temp[i]);
        }
        vm = warp_sum(vm);
        vt = warp_sum(vt);
        __shared__ double fm[BLOCK / 32];
        __shared__ double ft[BLOCK / 32];
        if (lane == 0) { fm[warp] = vm; ft[warp] = vt; }
        __syncthreads();
        if (warp == 0) {
            double qm = (lane < BLOCK / 32) ? fm[lane] : 0.0;
            double qt = (lane < BLOCK / 32) ? ft[lane] : 0.0;
#pragma unroll
            for (int o = 4; o > 0; o >>= 1) {
                qm += __shfl_down_sync(0xFFFFFFFFu, qm, o);
                qt += __shfl_down_sync(0xFFFFFFFFu, qt, o);
            }
            if (lane == 0) {
                double Lm = qm / N_MAIN;
                double Lt = qt / N_TEMP;
                out[0] = (float)(Lm + TAU * Lt);
                out[1] = (float)Lm;
                out[2] = (float)Lt;
            }
        }
    }
}

extern "C" void kernel_launch(void* const* d_in, const int* in_sizes, int n_in,
                              void* d_out, int out_size) {
    const float* xs = (const float*)d_in[0];   // x_star_T
    const float* xt = (const float*)d_in[1];   // x_target_T
    float* out = (float*)d_out;

    loss_fused_kernel<<<NBLK, BLOCK>>>(xs, xt, out);
}

// round 15
// speedup vs baseline: 1.0724x; 1.0724x over previous
#include <cuda_runtime.h>

// ---------------------------------------------------------------------------
// Problem shape (fixed by setup_inputs): [B=4, C=16, T=32, H=128, W=128] fp32
// out = (total, L_main, L_temp) as 3 fp32 scalars.
//
// Math: with e = x_star - x_tgt (linearity), e_low = D^T(De) where D = first
// K=4 orthonormal DCT-II rows. Temporal-diff energy = c^T (Q Q^T) c with
// c = De, Q[n,s] = D[n,s+1]-D[n,s]. DC row of D is constant -> Q row 0 == 0,
// so only c1..c3 are needed. Charbonnier ~ |e| (abs error <= eps = 1e-6).
//
// R15 = convergence submission. Measured plateau: the 2-column / 64-register
// shape hits 5.80-5.85 TB/s across three launch geometries (R8/R10/R13);
// 1-column runs 5.2 TB/s; a 48-reg squeeze runs 5.3 TB/s. Geometry, cache
// policy, row adjacency, and balance moved nothing. This is the best-total
// config (R10): BLOCK=128, grid=1024, __launch_bounds__(128,8) -> 64 regs,
// no spills, ~6.9 resident blocks/SM, plus the lean warp-segmented finalize
// and __ldcg streaming loads (bypass L1 fill for read-once data; cache
// policy measured neutral, so this is free).
// ---------------------------------------------------------------------------
constexpr int T_DIM  = 32;
constexpr int HW     = 128 * 128;      // 16384
constexpr int HW4    = HW / 4;         // 4096 float4 per (b,c,t) plane
constexpr int BC     = 4 * 16;         // 64
constexpr int BLOCK  = 128;
constexpr int NITEM  = BC * HW4;       // 262144 fiber columns (float4 wide)
constexpr int HALF   = NITEM / 2;      // 131072: items per position-slot
constexpr int NBLK   = HALF / BLOCK;   // 1024 blocks

constexpr double N_MAIN = 33554432.0;  // B*C*T*H*W
constexpr double N_TEMP = 32505856.0;  // B*C*(T-1)*H*W
constexpr double TAU    = 0.1;

// ---------------------------------------------------------------------------
// Compile-time DCT: D[n][t] = 0.25 * cos(pi*(2t+1)*n/64)   (sqrt(2/32)=0.25)
// ---------------------------------------------------------------------------
constexpr double PI_D = 3.141592653589793238462643383279502884;

__host__ __device__ constexpr double dcos(double x) {
    while (x >  PI_D) x -= 2.0 * PI_D;
    while (x < -PI_D) x += 2.0 * PI_D;
    double x2 = x * x;
    double term = 1.0, sum = 1.0;
    for (int k = 1; k <= 18; ++k) {
        term *= -x2 / ((2.0 * k - 1.0) * (2.0 * k));
        sum += term;
    }
    return sum;
}
__host__ __device__ constexpr double Dc(int n, int t) {
    return 0.25 * dcos(PI_D * (2.0 * t + 1.0) * (double)n / 64.0);
}
__host__ __device__ constexpr double Qc(int n, int s) { return Dc(n, s + 1) - Dc(n, s); }
__host__ __device__ constexpr double Mc(int n, int m) {
    double s = 0.0;
    for (int i = 0; i < T_DIM - 1; ++i) s += Qc(n, i) * Qc(m, i);
    return s;
}

// ---------------------------------------------------------------------------
// Scratch: per-block partials + self-resetting completion counter.
// atomicInc(&g_count, NBLK-1) wraps to 0 when the last block arrives, so the
// counter is 0 again at the start of every graph replay. No cleanup kernel.
// ---------------------------------------------------------------------------
__device__ double   g_part_main[NBLK];
__device__ double   g_part_temp[NBLK];
__device__ unsigned g_count = 0;

struct Acc {
    float4 c1, c2, c3;
    float  m0, m1;   // pairwise |e| accumulators (R8-proven shape)
};

__device__ __forceinline__ void proc(const float4& a, const float4& b,
                                     float d1, float d2, float d3, Acc& s) {
    float e0 = a.x - b.x, e1 = a.y - b.y, e2 = a.z - b.z, e3 = a.w - b.w;
    s.m0 += fabsf(e0) + fabsf(e1);
    s.m1 += fabsf(e2) + fabsf(e3);
    s.c1.x = fmaf(d1, e0, s.c1.x); s.c1.y = fmaf(d1, e1, s.c1.y);
    s.c1.z = fmaf(d1, e2, s.c1.z); s.c1.w = fmaf(d1, e3, s.c1.w);
    s.c2.x = fmaf(d2, e0, s.c2.x); s.c2.y = fmaf(d2, e1, s.c2.y);
    s.c2.z = fmaf(d2, e2, s.c2.z); s.c2.w = fmaf(d2, e3, s.c2.w);
    s.c3.x = fmaf(d3, e0, s.c3.x); s.c3.y = fmaf(d3, e1, s.c3.y);
    s.c3.z = fmaf(d3, e2, s.c3.z); s.c3.w = fmaf(d3, e3, s.c3.w);
}

// Template-unrolled T loop: coefficients are constexpr locals per step ->
// FFMA immediates in SASS. Two position slots per step, all four loads
// issued before the arithmetic for maximum per-step MLP. __ldcg: read-once
// data, skip L1 fill.
template <int t>
__device__ __forceinline__ void step_all(const float4* __restrict__ pa1,
                                         const float4* __restrict__ pb1,
                                         const float4* __restrict__ pa2,
                                         const float4* __restrict__ pb2,
                                         Acc& s1, Acc& s2) {
    if constexpr (t < T_DIM) {
        constexpr float d1 = (float)Dc(1, t);
        constexpr float d2 = (float)Dc(2, t);
        constexpr float d3 = (float)Dc(3, t);
        float4 a1 = __ldcg(pa1 + t * HW4);
        float4 b1 = __ldcg(pb1 + t * HW4);
        float4 a2 = __ldcg(pa2 + t * HW4);
        float4 b2 = __ldcg(pb2 + t * HW4);
        proc(a1, b1, d1, d2, d3, s1);
        proc(a2, b2, d1, d2, d3, s2);
        step_all<t + 1>(pa1, pb1, pa2, pb2, s1, s2);
    }
}

__device__ __forceinline__ float quad_form(float a, float b, float c) {
    constexpr float M11 = (float)Mc(1, 1);
    constexpr float M22 = (float)Mc(2, 2);
    constexpr float M33 = (float)Mc(3, 3);
    constexpr float M12 = (float)(2.0 * Mc(1, 2));
    constexpr float M13 = (float)(2.0 * Mc(1, 3));
    constexpr float M23 = (float)(2.0 * Mc(2, 3));
    float q = M11 * a * a;
    q = fmaf(M22 * b, b, q);
    q = fmaf(M33 * c, c, q);
    q = fmaf(M12 * a, b, q);
    q = fmaf(M13 * a, c, q);
    q = fmaf(M23 * b, c, q);
    return q;
}

__device__ __forceinline__ float quad4(const Acc& s) {
    return (quad_form(s.c1.x, s.c2.x, s.c3.x) + quad_form(s.c1.y, s.c2.y, s.c3.y))
         + (quad_form(s.c1.z, s.c2.z, s.c3.z) + quad_form(s.c1.w, s.c2.w, s.c3.w));
}

__device__ __forceinline__ const float4* fiber_ptr(const float* x, int g) {
    // item g -> (bc = g/4096, hw = g%4096); fiber base in float4 units
    int bc = g >> 12;
    int hw = g & (HW4 - 1);
    return reinterpret_cast<const float4*>(x) + (size_t)bc * (T_DIM * HW4) + hw;
}

__device__ __forceinline__ double warp_sum(double v) {
#pragma unroll
    for (int o = 16; o > 0; o >>= 1)
        v += __shfl_down_sync(0xFFFFFFFFu, v, o);
    return v;
}

__global__ void __launch_bounds__(BLOCK, 8)
loss_fused_kernel(const float* __restrict__ xs, const float* __restrict__ xt,
                  float* __restrict__ out) {
    const int tid = threadIdx.x;
    const int g1  = blockIdx.x * BLOCK + tid;   // position slot 1
    const int g2  = g1 + HALF;                  // position slot 2 (independent)

    const float4* pa1 = fiber_ptr(xs, g1);
    const float4* pb1 = fiber_ptr(xt, g1);
    const float4* pa2 = fiber_ptr(xs, g2);
    const float4* pb2 = fiber_ptr(xt, g2);

    Acc s1 = {}, s2 = {};

    step_all<0>(pa1, pb1, pa2, pb2, s1, s2);

    double tempv = (double)quad4(s1) + (double)quad4(s2);
    double mainv = (double)((s1.m0 + s1.m1) + (s2.m0 + s2.m1));

    // ---- intra-block reduce: warp shuffle + one shared stage ----
    const int lane = tid & 31;
    const int warp = tid >> 5;
    __shared__ double sm[BLOCK / 32];
    __shared__ double st[BLOCK / 32];

    mainv = warp_sum(mainv);
    tempv = warp_sum(tempv);
    if (lane == 0) { sm[warp] = mainv; st[warp] = tempv; }
    __syncthreads();

    __shared__ bool is_last;
    if (warp == 0) {
        double vm = (lane < BLOCK / 32) ? sm[lane] : 0.0;
        double vt = (lane < BLOCK / 32) ? st[lane] : 0.0;
#pragma unroll
        for (int o = 2; o > 0; o >>= 1) {
            vm += __shfl_down_sync(0xFFFFFFFFu, vm, o);
            vt += __shfl_down_sync(0xFFFFFFFFu, vt, o);
        }
        if (lane == 0) {
            g_part_main[blockIdx.x] = vm;
            g_part_temp[blockIdx.x] = vt;
            __threadfence();
            // wraps to 0 when old == NBLK-1 -> self-resetting across replays
            is_last = (atomicInc(&g_count, NBLK - 1) == NBLK - 1);
        }
    }
    __syncthreads();

    // ---- last-arriving block: deterministic fixed-order global reduce ----
    if (is_last) {
        double vm = 0.0, vt = 0.0;
#pragma unroll
        for (int i = tid; i < NBLK; i += BLOCK) {
            vm += __ldcg(&g_part_main[i]);
            vt += __ldcg(&g_part_temp[i]);
        }
        vm = warp_sum(vm);
        vt = warp_sum(vt);
        __shared__ double fm[BLOCK / 32];
        __shared__ double ft[BLOCK / 32];
        if (lane == 0) { fm[warp] = vm; ft[warp] = vt; }
        __syncthreads();
        if (warp == 0) {
            double qm = (lane < BLOCK / 32) ? fm[lane] : 0.0;
            double qt = (lane < BLOCK / 32) ? ft[lane] : 0.0;
#pragma unroll
            for (int o = 2; o > 0; o >>= 1) {
                qm += __shfl_down_sync(0xFFFFFFFFu, qm, o);
                qt += __shfl_down_sync(0xFFFFFFFFu, qt, o);
            }
            if (lane == 0) {
                double Lm = qm / N_MAIN;
                double Lt = qt / N_TEMP;
                out[0] = (float)(Lm + TAU * Lt);
                out[1] = (float)Lm;
                out[2] = (float)Lt;
            }
        }
    }
}

extern "C" void kernel_launch(void* const* d_in, const int* in_sizes, int n_in,
                              void* d_out, int out_size) {
    const float* xs = (const float*)d_in[0];   // x_star_T
    const float* xt = (const float*)d_in[1];   // x_target_T
    float* out = (float*)d_out;

    loss_fused_kernel<<<NBLK, BLOCK>>>(xs, xt, out);
}

// round 16
// speedup vs baseline: 1.0746x; 1.0020x over previous
#include <cuda_runtime.h>

// ---------------------------------------------------------------------------
// Problem shape (fixed by setup_inputs): [B=4, C=16, T=32, H=128, W=128] fp32
// out = (total, L_main, L_temp) as 3 fp32 scalars.
//
// Math: with e = x_star - x_tgt (linearity), e_low = D^T(De) where D = first
// K=4 orthonormal DCT-II rows. Temporal-diff energy = c^T (Q Q^T) c with
// c = De, Q[n,s] = D[n,s+1]-D[n,s]. DC row of D is constant -> Q row 0 == 0,
// so only c1..c3 are needed. Charbonnier ~ |e| (abs error <= eps = 1e-6).
//
// FINAL (converged): 2 columns/thread, 4 independent 128-bit load streams,
// BLOCK=128, grid=1024, __launch_bounds__(128,8) -> 64 regs, no spills.
// Measured plateau 5.80-5.86 TB/s across five geometry/policy variants;
// kernel time within 1.5% of its own bandwidth floor (268.4MB / 5.86TB/s).
// Probes that regressed or were neutral: 1-col (5.2TB/s), 48-reg squeeze
// (5.3TB/s), heavy/light split (spilled), row adjacency, __ldcs, balance.
// Fused deterministic finalize via self-resetting atomicInc (graph-safe).
// ---------------------------------------------------------------------------
constexpr int T_DIM  = 32;
constexpr int HW     = 128 * 128;      // 16384
constexpr int HW4    = HW / 4;         // 4096 float4 per (b,c,t) plane
constexpr int BC     = 4 * 16;         // 64
constexpr int BLOCK  = 128;
constexpr int NITEM  = BC * HW4;       // 262144 fiber columns (float4 wide)
constexpr int HALF   = NITEM / 2;      // 131072: items per position-slot
constexpr int NBLK   = HALF / BLOCK;   // 1024 blocks

constexpr double N_MAIN = 33554432.0;  // B*C*T*H*W
constexpr double N_TEMP = 32505856.0;  // B*C*(T-1)*H*W
constexpr double TAU    = 0.1;

// ---------------------------------------------------------------------------
// Compile-time DCT: D[n][t] = 0.25 * cos(pi*(2t+1)*n/64)   (sqrt(2/32)=0.25)
// ---------------------------------------------------------------------------
constexpr double PI_D = 3.141592653589793238462643383279502884;

__host__ __device__ constexpr double dcos(double x) {
    while (x >  PI_D) x -= 2.0 * PI_D;
    while (x < -PI_D) x += 2.0 * PI_D;
    double x2 = x * x;
    double term = 1.0, sum = 1.0;
    for (int k = 1; k <= 18; ++k) {
        term *= -x2 / ((2.0 * k - 1.0) * (2.0 * k));
        sum += term;
    }
    return sum;
}
__host__ __device__ constexpr double Dc(int n, int t) {
    return 0.25 * dcos(PI_D * (2.0 * t + 1.0) * (double)n / 64.0);
}
__host__ __device__ constexpr double Qc(int n, int s) { return Dc(n, s + 1) - Dc(n, s); }
__host__ __device__ constexpr double Mc(int n, int m) {
    double s = 0.0;
    for (int i = 0; i < T_DIM - 1; ++i) s += Qc(n, i) * Qc(m, i);
    return s;
}

// ---------------------------------------------------------------------------
// Scratch: per-block partials + self-resetting completion counter.
// atomicInc(&g_count, NBLK-1) wraps to 0 when the last block arrives, so the
// counter is 0 again at the start of every graph replay. No cleanup kernel.
// ---------------------------------------------------------------------------
__device__ double   g_part_main[NBLK];
__device__ double   g_part_temp[NBLK];
__device__ unsigned g_count = 0;

struct Acc {
    float4 c1, c2, c3;
    float  m0, m1;   // pairwise |e| accumulators
};

__device__ __forceinline__ void proc(const float4& a, const float4& b,
                                     float d1, float d2, float d3, Acc& s) {
    float e0 = a.x - b.x, e1 = a.y - b.y, e2 = a.z - b.z, e3 = a.w - b.w;
    s.m0 += fabsf(e0) + fabsf(e1);
    s.m1 += fabsf(e2) + fabsf(e3);
    s.c1.x = fmaf(d1, e0, s.c1.x); s.c1.y = fmaf(d1, e1, s.c1.y);
    s.c1.z = fmaf(d1, e2, s.c1.z); s.c1.w = fmaf(d1, e3, s.c1.w);
    s.c2.x = fmaf(d2, e0, s.c2.x); s.c2.y = fmaf(d2, e1, s.c2.y);
    s.c2.z = fmaf(d2, e2, s.c2.z); s.c2.w = fmaf(d2, e3, s.c2.w);
    s.c3.x = fmaf(d3, e0, s.c3.x); s.c3.y = fmaf(d3, e1, s.c3.y);
    s.c3.z = fmaf(d3, e2, s.c3.z); s.c3.w = fmaf(d3, e3, s.c3.w);
}

// Template-unrolled T loop: coefficients are constexpr locals per step ->
// FFMA immediates in SASS. Two position slots per step, all four loads
// issued before the arithmetic for maximum per-step MLP. __ldcg: read-once
// data, skip L1 fill.
template <int t>
__device__ __forceinline__ void step_all(const float4* __restrict__ pa1,
                                         const float4* __restrict__ pb1,
                                         const float4* __restrict__ pa2,
                                         const float4* __restrict__ pb2,
                                         Acc& s1, Acc& s2) {
    if constexpr (t < T_DIM) {
        constexpr float d1 = (float)Dc(1, t);
        constexpr float d2 = (float)Dc(2, t);
        constexpr float d3 = (float)Dc(3, t);
        float4 a1 = __ldcg(pa1 + t * HW4);
        float4 b1 = __ldcg(pb1 + t * HW4);
        float4 a2 = __ldcg(pa2 + t * HW4);
        float4 b2 = __ldcg(pb2 + t * HW4);
        proc(a1, b1, d1, d2, d3, s1);
        proc(a2, b2, d1, d2, d3, s2);
        step_all<t + 1>(pa1, pb1, pa2, pb2, s1, s2);
    }
}

__device__ __forceinline__ float quad_form(float a, float b, float c) {
    constexpr float M11 = (float)Mc(1, 1);
    constexpr float M22 = (float)Mc(2, 2);
    constexpr float M33 = (float)Mc(3, 3);
    constexpr float M12 = (float)(2.0 * Mc(1, 2));
    constexpr float M13 = (float)(2.0 * Mc(1, 3));
    constexpr float M23 = (float)(2.0 * Mc(2, 3));
    float q = M11 * a * a;
    q = fmaf(M22 * b, b, q);
    q = fmaf(M33 * c, c, q);
    q = fmaf(M12 * a, b, q);
    q = fmaf(M13 * a, c, q);
    q = fmaf(M23 * b, c, q);
    return q;
}

__device__ __forceinline__ float quad4(const Acc& s) {
    return (quad_form(s.c1.x, s.c2.x, s.c3.x) + quad_form(s.c1.y, s.c2.y, s.c3.y))
         + (quad_form(s.c1.z, s.c2.z, s.c3.z) + quad_form(s.c1.w, s.c2.w, s.c3.w));
}

__device__ __forceinline__ const float4* fiber_ptr(const float* x, int g) {
    // item g -> (bc = g/4096, hw = g%4096); fiber base in float4 units
    int bc = g >> 12;
    int hw = g & (HW4 - 1);
    return reinterpret_cast<const float4*>(x) + (size_t)bc * (T_DIM * HW4) + hw;
}

__device__ __forceinline__ double warp_sum(double v) {
#pragma unroll
    for (int o = 16; o > 0; o >>= 1)
        v += __shfl_down_sync(0xFFFFFFFFu, v, o);
    return v;
}

__global__ void __launch_bounds__(BLOCK, 8)
loss_fused_kernel(const float* __restrict__ xs, const float* __restrict__ xt,
                  float* __restrict__ out) {
    const int tid = threadIdx.x;
    const int g1  = blockIdx.x * BLOCK + tid;   // position slot 1
    const int g2  = g1 + HALF;                  // position slot 2 (independent)

    const float4* pa1 = fiber_ptr(xs, g1);
    const float4* pb1 = fiber_ptr(xt, g1);
    const float4* pa2 = fiber_ptr(xs, g2);
    const float4* pb2 = fiber_ptr(xt, g2);

    Acc s1 = {}, s2 = {};

    step_all<0>(pa1, pb1, pa2, pb2, s1, s2);

    double tempv = (double)quad4(s1) + (double)quad4(s2);
    double mainv = (double)((s1.m0 + s1.m1) + (s2.m0 + s2.m1));

    // ---- intra-block reduce: warp shuffle + one shared stage ----
    const int lane = tid & 31;
    const int warp = tid >> 5;
    __shared__ double sm[BLOCK / 32];
    __shared__ double st[BLOCK / 32];

    mainv = warp_sum(mainv);
    tempv = warp_sum(tempv);
    if (lane == 0) { sm[warp] = mainv; st[warp] = tempv; }
    __syncthreads();

    __shared__ bool is_last;
    if (warp == 0) {
        double vm = (lane < BLOCK / 32) ? sm[lane] : 0.0;
        double vt = (lane < BLOCK / 32) ? st[lane] : 0.0;
#pragma unroll
        for (int o = 2; o > 0; o >>= 1) {
            vm += __shfl_down_sync(0xFFFFFFFFu, vm, o);
            vt += __shfl_down_sync(0xFFFFFFFFu, vt, o);
        }
        if (lane == 0) {
            g_part_main[blockIdx.x] = vm;
            g_part_temp[blockIdx.x] = vt;
            __threadfence();
            // wraps to 0 when old == NBLK-1 -> self-resetting across replays
            is_last = (atomicInc(&g_count, NBLK - 1) == NBLK - 1);
        }
    }
    __syncthreads();

    // ---- last-arriving block: deterministic fixed-order global reduce ----
    if (is_last) {
        double vm = 0.0, vt = 0.0;
#pragma unroll
        for (int i = tid; i < NBLK; i += BLOCK) {
            vm += __ldcg(&g_part_main[i]);
            vt += __ldcg(&g_part_temp[i]);
        }
        vm = warp_sum(vm);
        vt = warp_sum(vt);
        __shared__ double fm[BLOCK / 32];
        __shared__ double ft[BLOCK / 32];
        if (lane == 0) { fm[warp] = vm; ft[warp] = vt; }
        __syncthreads();
        if (warp == 0) {
            double qm = (lane < BLOCK / 32) ? fm[lane] : 0.0;
            double qt = (lane < BLOCK / 32) ? ft[lane] : 0.0;
#pragma unroll
            for (int o = 2; o > 0; o >>= 1) {
                qm += __shfl_down_sync(0xFFFFFFFFu, qm, o);
                qt += __shfl_down_sync(0xFFFFFFFFu, qt, o);
            }
            if (lane == 0) {
                double Lm = qm / N_MAIN;
                double Lt = qt / N_TEMP;
                out[0] = (float)(Lm + TAU * Lt);
                out[1] = (float)Lm;
                out[2] = (float)Lt;
            }
        }
    }
}

extern "C" void kernel_launch(void* const* d_in, const int* in_sizes, int n_in,
                              void* d_out, int out_size) {
    const float* xs = (const float*)d_in[0];   // x_star_T
    const float* xt = (const float*)d_in[1];   // x_target_T
    float* out = (float*)d_out;

    loss_fused_kernel<<<NBLK, BLOCK>>>(xs, xt, out);
}